// round 2
// baseline (speedup 1.0000x reference)
#include <cuda_runtime.h>
#include <cuda_bf16.h>
#include <math.h>

#define NN 100000
#define EE 3200000
#define NEMAX (EE + NN)

// ---------------- scratch (device globals; no allocation allowed) ----------
__device__ float g_xp1[NN * 32];          // x @ W1
__device__ float g_as1[NN * 4];           // alpha_src per node/head (layer 1)
__device__ float g_ad1[NN * 4];           // alpha_dst per node/head (layer 1)
__device__ float g_h[NN * 32];            // elu(conv1 out)
__device__ float g_xp2[NN * 8];           // h @ W2
__device__ float g_as2[NN];
__device__ float g_ad2[NN];
__device__ int   g_deg[NN];
__device__ int   g_off[NN];
__device__ int   g_pos[NN];
__device__ int   g_csr[NEMAX];            // src node per CSR slot (grouped by dst)
__device__ float g_p[(size_t)NEMAX * 4];  // unnormalized softmax numerators
__device__ int   g_total;

// ---------------- init: self-loop degree = 1, reset cursor -----------------
__global__ void init_kernel() {
    int n = blockIdx.x * blockDim.x + threadIdx.x;
    if (n < NN) g_deg[n] = 1;
    if (n == 0) g_total = 0;
}

// ---------------- GEMM1: xp1 = x[N,512] @ W1[512,32] -----------------------
__global__ void gemm1_kernel(const float* __restrict__ x,
                             const float* __restrict__ W) {
    __shared__ float xs[128][36];   // pad 36: float4-aligned rows, low conflict
    __shared__ float ws[32][32];
    int t = threadIdx.x;
    int row0 = blockIdx.x * 128;
    int rg = t >> 3;                 // 0..31 row-group
    int cg = (t & 7) << 2;           // 0,4,...,28 col base
    int r4 = rg << 2;                // 4 rows per thread
    float acc[4][4];
#pragma unroll
    for (int i = 0; i < 4; i++)
#pragma unroll
        for (int j = 0; j < 4; j++) acc[i][j] = 0.f;

    for (int kk = 0; kk < 512; kk += 32) {
        // load x tile [128][32]
#pragma unroll
        for (int i = 0; i < 4; i++) {
            int lf = i * 256 + t;            // 0..1023 float4 groups
            int r  = lf >> 3;
            int k4 = (lf & 7) << 2;
            float4 v = make_float4(0.f, 0.f, 0.f, 0.f);
            int grow = row0 + r;
            if (grow < NN)
                v = *(const float4*)(x + (size_t)grow * 512 + kk + k4);
            *(float4*)(&xs[r][k4]) = v;
        }
        // load W tile [32][32]
        {
            int r  = t >> 3;
            int k4 = (t & 7) << 2;
            float4 v = *(const float4*)(W + (size_t)(kk + r) * 32 + k4);
            *(float4*)(&ws[r][k4]) = v;
        }
        __syncthreads();
#pragma unroll
        for (int k = 0; k < 32; k++) {
            float4 wv = *(float4*)(&ws[k][cg]);
#pragma unroll
            for (int i = 0; i < 4; i++) {
                float xv = xs[r4 + i][k];
                acc[i][0] += xv * wv.x;
                acc[i][1] += xv * wv.y;
                acc[i][2] += xv * wv.z;
                acc[i][3] += xv * wv.w;
            }
        }
        __syncthreads();
    }
#pragma unroll
    for (int i = 0; i < 4; i++) {
        int grow = row0 + r4 + i;
        if (grow < NN)
            *(float4*)(g_xp1 + (size_t)grow * 32 + cg) =
                make_float4(acc[i][0], acc[i][1], acc[i][2], acc[i][3]);
    }
}

// ------------- per-node attention projections, layer 1 ---------------------
__global__ void attn1_kernel(const float* __restrict__ att_src,
                             const float* __restrict__ att_dst) {
    int idx = blockIdx.x * blockDim.x + threadIdx.x;  // (n, h)
    if (idx >= NN * 4) return;
    int n = idx >> 2, h = idx & 3;
    const float* xp = g_xp1 + (size_t)n * 32 + h * 8;
    float s = 0.f, d = 0.f;
#pragma unroll
    for (int c = 0; c < 8; c++) {
        float v = xp[c];
        s += v * att_src[h * 8 + c];
        d += v * att_dst[h * 8 + c];
    }
    g_as1[idx] = s;
    g_ad1[idx] = d;
}

// ---------------- CSR build --------------------------------------------------
__global__ void count_kernel(const int* __restrict__ dst, int E) {
    int i = blockIdx.x * blockDim.x + threadIdx.x;
    if (i < E) atomicAdd(&g_deg[dst[i]], 1);
}

__global__ void alloc_kernel() {
    int n = blockIdx.x * blockDim.x + threadIdx.x;
    int lane = threadIdx.x & 31;
    int deg = (n < NN) ? g_deg[n] : 0;
    int scan = deg;
#pragma unroll
    for (int d = 1; d < 32; d <<= 1) {
        int tv = __shfl_up_sync(0xffffffffu, scan, d);
        if (lane >= d) scan += tv;
    }
    int total = __shfl_sync(0xffffffffu, scan, 31);
    int base = 0;
    if (lane == 31) base = atomicAdd(&g_total, total);
    base = __shfl_sync(0xffffffffu, base, 31);
    int off = base + scan - deg;
    if (n < NN) {
        g_off[n] = off;
        g_csr[off] = n;       // self-loop in slot 0
        g_pos[n] = off + 1;
    }
}

__global__ void scatter_kernel(const int* __restrict__ src,
                               const int* __restrict__ dst, int E) {
    int i = blockIdx.x * blockDim.x + threadIdx.x;
    if (i >= E) return;
    int d = dst[i];
    int slot = atomicAdd(&g_pos[d], 1);
    g_csr[slot] = src[i];
}

// --------- layer-1 segment softmax + aggregation: one warp per dst ---------
__global__ void l1_kernel(const float* __restrict__ b1) {
    int warp = (blockIdx.x * blockDim.x + threadIdx.x) >> 5;
    int lane = threadIdx.x & 31;
    int n = warp;
    if (n >= NN) return;
    int off = g_off[n], deg = g_deg[n];

    // phase A/B layout: lane = j*4 + h (8 edges x 4 heads per chunk)
    int h = lane & 3, j = lane >> 2;
    float adh = g_ad1[n * 4 + h];

    float m = -1e30f;
    for (int base = 0; base < deg; base += 8) {
        int idx = base + j;
        float e = -1e30f;
        if (idx < deg) {
            int s = g_csr[off + idx];
            float v = g_as1[s * 4 + h] + adh;
            e = v > 0.f ? v : 0.2f * v;
        }
        m = fmaxf(m, e);
    }
    m = fmaxf(m, __shfl_xor_sync(0xffffffffu, m, 4));
    m = fmaxf(m, __shfl_xor_sync(0xffffffffu, m, 8));
    m = fmaxf(m, __shfl_xor_sync(0xffffffffu, m, 16));

    float sum = 0.f;
    for (int base = 0; base < deg; base += 8) {
        int idx = base + j;
        if (idx < deg) {
            int s = g_csr[off + idx];
            float v = g_as1[s * 4 + h] + adh;
            float e = v > 0.f ? v : 0.2f * v;
            float p = __expf(e - m);
            g_p[(size_t)(off + idx) * 4 + h] = p;
            sum += p;
        }
    }
    sum += __shfl_xor_sync(0xffffffffu, sum, 4);
    sum += __shfl_xor_sync(0xffffffffu, sum, 8);
    sum += __shfl_xor_sync(0xffffffffu, sum, 16);
    float invd = 1.f / sum;

    __threadfence_block();
    __syncwarp();

    // phase C layout: lane = h*8 + c
    int hC = lane >> 3;
    float invdC = __shfl_sync(0xffffffffu, invd, hC);  // lane hC holds head hC
    float acc = 0.f;
    for (int jj = 0; jj < deg; jj++) {
        int s = g_csr[off + jj];
        float p = g_p[(size_t)(off + jj) * 4 + hC];
        acc += p * g_xp1[(size_t)s * 32 + lane];
    }
    float out = acc * invdC + b1[lane];
    g_h[(size_t)n * 32 + lane] = out > 0.f ? out : expm1f(out);
}

// -------- layer-2 projection + attention coeffs: warp per 4 nodes ----------
__global__ void xp2_kernel(const float* __restrict__ W2,
                           const float* __restrict__ att_src,
                           const float* __restrict__ att_dst) {
    int gid = blockIdx.x * blockDim.x + threadIdx.x;
    int lane = threadIdx.x & 31;
    int n = ((gid >> 5) << 2) + (lane >> 3);  // 4 nodes per warp
    int c = lane & 7;
    float acc = 0.f;
    if (n < NN) {
        const float* hrow = g_h + (size_t)n * 32;
#pragma unroll
        for (int k = 0; k < 32; k++) acc += hrow[k] * W2[k * 8 + c];
        g_xp2[(size_t)n * 8 + c] = acc;
    }
    float s = (n < NN) ? acc * att_src[c] : 0.f;
    float d = (n < NN) ? acc * att_dst[c] : 0.f;
#pragma unroll
    for (int dd = 1; dd < 8; dd <<= 1) {
        s += __shfl_xor_sync(0xffffffffu, s, dd);
        d += __shfl_xor_sync(0xffffffffu, d, dd);
    }
    if (n < NN && c == 0) {
        g_as2[n] = s;
        g_ad2[n] = d;
    }
}

// --------- layer-2 segment softmax + aggregation: one warp per dst ---------
__global__ void l2_kernel(float* __restrict__ out, const float* __restrict__ b2) {
    int warp = (blockIdx.x * blockDim.x + threadIdx.x) >> 5;
    int lane = threadIdx.x & 31;
    int n = warp;
    if (n >= NN) return;
    int off = g_off[n], deg = g_deg[n];
    float adn = g_ad2[n];

    float m = -1e30f;
    for (int base = 0; base < deg; base += 32) {
        int idx = base + lane;
        float e = -1e30f;
        if (idx < deg) {
            int s = g_csr[off + idx];
            float v = g_as2[s] + adn;
            e = v > 0.f ? v : 0.2f * v;
        }
        m = fmaxf(m, e);
    }
#pragma unroll
    for (int d = 1; d < 32; d <<= 1)
        m = fmaxf(m, __shfl_xor_sync(0xffffffffu, m, d));

    float sum = 0.f;
    for (int base = 0; base < deg; base += 32) {
        int idx = base + lane;
        if (idx < deg) {
            int s = g_csr[off + idx];
            float v = g_as2[s] + adn;
            float e = v > 0.f ? v : 0.2f * v;
            float p = __expf(e - m);
            g_p[off + idx] = p;
            sum += p;
        }
    }
#pragma unroll
    for (int d = 1; d < 32; d <<= 1)
        sum += __shfl_xor_sync(0xffffffffu, sum, d);
    float invd = 1.f / sum;

    __threadfence_block();
    __syncwarp();

    // accumulate layout: lane = jj*8 + c (4 edges x 8 channels)
    int c = lane & 7, jj = lane >> 3;
    float acc = 0.f;
    for (int base = 0; base < deg; base += 4) {
        int idx = base + jj;
        if (idx < deg) {
            int s = g_csr[off + idx];
            acc += g_p[off + idx] * g_xp2[(size_t)s * 8 + c];
        }
    }
    acc += __shfl_xor_sync(0xffffffffu, acc, 8);
    acc += __shfl_xor_sync(0xffffffffu, acc, 16);
    if (lane < 8) out[(size_t)n * 8 + lane] = acc * invd + b2[lane];
}

// ---------------------------------------------------------------------------
extern "C" void kernel_launch(void* const* d_in, const int* in_sizes, int n_in,
                              void* d_out, int out_size) {
    const float* x        = (const float*)d_in[0];
    const int*   eidx     = (const int*)d_in[1];
    const float* W1       = (const float*)d_in[2];
    const float* att_src1 = (const float*)d_in[3];
    const float* att_dst1 = (const float*)d_in[4];
    const float* b1       = (const float*)d_in[5];
    const float* W2       = (const float*)d_in[6];
    const float* att_src2 = (const float*)d_in[7];
    const float* att_dst2 = (const float*)d_in[8];
    const float* b2       = (const float*)d_in[9];
    float* out = (float*)d_out;

    int E = in_sizes[1] / 2;
    const int* src = eidx;
    const int* dst = eidx + E;

    init_kernel<<<(NN + 255) / 256, 256>>>();
    gemm1_kernel<<<(NN + 127) / 128, 256>>>(x, W1);
    attn1_kernel<<<(NN * 4 + 255) / 256, 256>>>(att_src1, att_dst1);
    count_kernel<<<(E + 255) / 256, 256>>>(dst, E);
    alloc_kernel<<<(NN + 255) / 256, 256>>>();
    scatter_kernel<<<(E + 255) / 256, 256>>>(src, dst, E);
    l1_kernel<<<(NN + 7) / 8, 256>>>(b1);
    xp2_kernel<<<(NN + 31) / 32, 256>>>(W2, att_src2, att_dst2);
    l2_kernel<<<(NN + 7) / 8, 256>>>(out, b2);
}

// round 3
// speedup vs baseline: 1.1695x; 1.1695x over previous
#include <cuda_runtime.h>
#include <cuda_bf16.h>
#include <math.h>

#define NN 100000
#define EE 3200000
#define NEMAX (EE + NN)
#define GEMMB 391          // ceil(NN/256) gemm blocks (256 rows each)
#define CNTB 256           // count blocks fused into k1
#define PADT 260           // padded row length of transposed x tile (even!)

typedef unsigned long long ull;

// ---------------- scratch (device globals; no allocation allowed) ----------
__device__ float g_xp1[NN * 32];   // x @ W1
__device__ float g_as1[NN * 4];
__device__ float g_ad1[NN * 4];
__device__ float g_xp2[NN * 8];    // h @ W2
__device__ float g_as2[NN];
__device__ float g_ad2[NN];
__device__ int   g_deg[NN];        // zero-init; reset to 0 by alloc each run
__device__ int   g_degN[NN];       // degree incl self-loop, for l1/l2
__device__ int   g_off[NN];
__device__ int   g_pos[NN];
__device__ int   g_csr[NEMAX];
__device__ int   g_total;          // zero-init; reset to 0 by scatter each run

// ---------------- packed f32x2 helpers ------------------------------------
__device__ __forceinline__ ull dup2(float v) {
    ull r; unsigned u = __float_as_uint(v);
    asm("mov.b64 %0, {%1, %1};" : "=l"(r) : "r"(u));
    return r;
}
__device__ __forceinline__ ull fma2(ull a, ull b, ull c) {
    ull d;
    asm("fma.rn.f32x2 %0, %1, %2, %3;" : "=l"(d) : "l"(a), "l"(b), "l"(c));
    return d;
}
__device__ __forceinline__ void unpack2(ull v, float& lo, float& hi) {
    unsigned a, b;
    asm("mov.b64 {%0, %1}, %2;" : "=r"(a), "=r"(b) : "l"(v));
    lo = __uint_as_float(a); hi = __uint_as_float(b);
}

// ============ K1: fused [GEMM1 + attn1 epilogue] & [degree count] ==========
// gemm blocks: tile 256 rows x 32 cols, thread = 8 rows x 4 cols,
// row-pairs packed in f32x2, x tile stored k-major (transposed) in smem.
__global__ __launch_bounds__(256) void k1_gemm_count(
    const float* __restrict__ x, const float* __restrict__ W,
    const float* __restrict__ as1, const float* __restrict__ ad1,
    const int* __restrict__ dst, int E)
{
    if (blockIdx.x >= GEMMB) {                 // ---- count blocks ----
        int i = (blockIdx.x - GEMMB) * 256 + threadIdx.x;
        for (; i < E; i += CNTB * 256) atomicAdd(&g_deg[dst[i]], 1);
        return;
    }
    __shared__ float xs[32 * PADT];            // [k][row] transposed
    __shared__ float ws[32 * 32];              // [k][col]
    int t = threadIdx.x;
    int row0 = blockIdx.x * 256;
    int rg  = t >> 3;                          // 0..31 -> rows rg*8..rg*8+7
    int cg4 = (t & 7) << 2;                    // 0,4,...,28 col base

    ull acc[4][4];
#pragma unroll
    for (int p = 0; p < 4; p++)
#pragma unroll
        for (int c = 0; c < 4; c++) acc[p][c] = 0ull;

    for (int kk = 0; kk < 512; kk += 32) {
        // load x tile transposed: 256 rows x 32 k
#pragma unroll
        for (int i = 0; i < 8; i++) {
            int lf  = i * 256 + t;             // 0..2047 float4 slots
            int row = lf >> 3;
            int k4  = (lf & 7) << 2;
            float4 v = make_float4(0.f, 0.f, 0.f, 0.f);
            int grow = row0 + row;
            if (grow < NN)
                v = *(const float4*)(x + (size_t)grow * 512 + kk + k4);
            xs[(k4 + 0) * PADT + row] = v.x;
            xs[(k4 + 1) * PADT + row] = v.y;
            xs[(k4 + 2) * PADT + row] = v.z;
            xs[(k4 + 3) * PADT + row] = v.w;
        }
        {   // load W tile [32 k][32 cols]
            int r = t >> 3, k4 = (t & 7) << 2;
            *(float4*)&ws[r * 32 + k4] = *(const float4*)(W + (size_t)(kk + r) * 32 + k4);
        }
        __syncthreads();
#pragma unroll
        for (int k = 0; k < 32; k++) {
            float4 wv = *(float4*)&ws[k * 32 + cg4];
            ull w0 = dup2(wv.x), w1 = dup2(wv.y), w2 = dup2(wv.z), w3 = dup2(wv.w);
            const ull* xr = (const ull*)&xs[k * PADT + (rg << 3)];
            ull x0 = xr[0], x1 = xr[1], x2 = xr[2], x3 = xr[3];
            acc[0][0] = fma2(x0, w0, acc[0][0]); acc[0][1] = fma2(x0, w1, acc[0][1]);
            acc[0][2] = fma2(x0, w2, acc[0][2]); acc[0][3] = fma2(x0, w3, acc[0][3]);
            acc[1][0] = fma2(x1, w0, acc[1][0]); acc[1][1] = fma2(x1, w1, acc[1][1]);
            acc[1][2] = fma2(x1, w2, acc[1][2]); acc[1][3] = fma2(x1, w3, acc[1][3]);
            acc[2][0] = fma2(x2, w0, acc[2][0]); acc[2][1] = fma2(x2, w1, acc[2][1]);
            acc[2][2] = fma2(x2, w2, acc[2][2]); acc[2][3] = fma2(x2, w3, acc[2][3]);
            acc[3][0] = fma2(x3, w0, acc[3][0]); acc[3][1] = fma2(x3, w1, acc[3][1]);
            acc[3][2] = fma2(x3, w2, acc[3][2]); acc[3][3] = fma2(x3, w3, acc[3][3]);
        }
        __syncthreads();
    }

    // epilogue: store xp1 + fused attention projections
    int head = cg4 >> 3;            // 0..3
    int half = (cg4 >> 2) & 1;      // which half of the head this thread holds
    float a_s[4], a_d[4];
#pragma unroll
    for (int c = 0; c < 4; c++) {
        a_s[c] = as1[head * 8 + half * 4 + c];
        a_d[c] = ad1[head * 8 + half * 4 + c];
    }
#pragma unroll
    for (int p = 0; p < 4; p++) {
        float o0[4], o1[4];
#pragma unroll
        for (int c = 0; c < 4; c++) unpack2(acc[p][c], o0[c], o1[c]);
#pragma unroll
        for (int rr = 0; rr < 2; rr++) {
            float* o = rr ? o1 : o0;
            int row = row0 + (rg << 3) + (p << 1) + rr;
            float sv = o[0]*a_s[0] + o[1]*a_s[1] + o[2]*a_s[2] + o[3]*a_s[3];
            float dv = o[0]*a_d[0] + o[1]*a_d[1] + o[2]*a_d[2] + o[3]*a_d[3];
            sv += __shfl_xor_sync(0xffffffffu, sv, 1);   // combine head halves
            dv += __shfl_xor_sync(0xffffffffu, dv, 1);
            if (row < NN) {
                *(float4*)(g_xp1 + (size_t)row * 32 + cg4) =
                    make_float4(o[0], o[1], o[2], o[3]);
                if (half == 0) g_as1[row * 4 + head] = sv;
                else           g_ad1[row * 4 + head] = dv;
            }
        }
    }
}

// ---------------- CSR alloc (also resets g_deg for next replay) ------------
__global__ void alloc_kernel() {
    int n = blockIdx.x * blockDim.x + threadIdx.x;
    int lane = threadIdx.x & 31;
    int deg = (n < NN) ? g_deg[n] + 1 : 0;     // +1 self-loop
    int scan = deg;
#pragma unroll
    for (int d = 1; d < 32; d <<= 1) {
        int tv = __shfl_up_sync(0xffffffffu, scan, d);
        if (lane >= d) scan += tv;
    }
    int total = __shfl_sync(0xffffffffu, scan, 31);
    int base = 0;
    if (lane == 31) base = atomicAdd(&g_total, total);
    base = __shfl_sync(0xffffffffu, base, 31);
    int off = base + scan - deg;
    if (n < NN) {
        g_off[n]  = off;
        g_csr[off] = n;        // self-loop in slot 0
        g_pos[n]  = off + 1;
        g_degN[n] = deg;
        g_deg[n]  = 0;         // ready for next replay's count
    }
}

__global__ void scatter_kernel(const int* __restrict__ src,
                               const int* __restrict__ dst, int E) {
    if (blockIdx.x == 0 && threadIdx.x == 0) g_total = 0;  // next replay
    int i = blockIdx.x * blockDim.x + threadIdx.x;
    if (i >= E) return;
    int d = dst[i];
    int slot = atomicAdd(&g_pos[d], 1);
    g_csr[slot] = src[i];
}

// ========== l1: single-pass softmax+aggregate, fused ELU + xp2/as2/ad2 =====
__global__ __launch_bounds__(256) void l1_kernel(
    const float* __restrict__ b1, const float* __restrict__ W2,
    const float* __restrict__ as2v, const float* __restrict__ ad2v)
{
    __shared__ float W2s[256];
    __shared__ float hs[8][33];
    int t = threadIdx.x;
    W2s[t] = W2[t];
    __syncthreads();

    int wid = t >> 5, lane = t & 31;
    int n = blockIdx.x * 8 + wid;              // grid 12500*8 == NN exactly
    int off = g_off[n], deg = g_degN[n];
    int hh = lane & 3, j4 = lane >> 2, hsel = lane >> 3;
    float adh = g_ad1[n * 4 + hh];

    float acc = 0.f, sum = 0.f;
    for (int base = 0; base < deg; base += 32) {
        int sjv = 0;
        if (base + lane < deg) sjv = g_csr[off + base + lane];
#pragma unroll
        for (int sub = 0; sub < 4; sub++) {
            int idx0 = base + (sub << 3);
            if (idx0 >= deg) break;
            // batched p: lane = (j4, hh) covers 8 edges x 4 heads
            int s8 = __shfl_sync(0xffffffffu, sjv, (sub << 3) + j4);
            float v = g_as1[s8 * 4 + hh] + adh;
            v = fmaxf(v, 0.2f * v);            // leaky relu
            float p = (idx0 + j4 < deg) ? __expf(v) : 0.f;
            sum += p;
#pragma unroll
            for (int j2 = 0; j2 < 8; j2++) {
                int sl = (sub << 3) + j2;
                int s = __shfl_sync(0xffffffffu, sjv, sl);
                float pb = __shfl_sync(0xffffffffu, p, (j2 << 2) | hsel);
                acc = fmaf(pb, g_xp1[(size_t)s * 32 + lane], acc);
            }
        }
    }
    // per-head denominators (reduce over j lanes)
    sum += __shfl_xor_sync(0xffffffffu, sum, 4);
    sum += __shfl_xor_sync(0xffffffffu, sum, 8);
    sum += __shfl_xor_sync(0xffffffffu, sum, 16);
    float invd = 1.f / sum;                     // lane's value = head (lane&3)
    float invs = __shfl_sync(0xffffffffu, invd, hsel);
    float o = fmaf(acc, invs, b1[lane]);
    float hval = o > 0.f ? o : expm1f(o);       // ELU

    // fused xp2 = h @ W2, plus as2/ad2
    hs[wid][lane] = hval;
    __syncwarp();
    if (lane < 8) {
        float s2 = 0.f;
#pragma unroll
        for (int k2 = 0; k2 < 32; k2++)
            s2 = fmaf(hs[wid][k2], W2s[k2 * 8 + lane], s2);
        g_xp2[(size_t)n * 8 + lane] = s2;
        float a = s2 * as2v[lane], d = s2 * ad2v[lane];
        a += __shfl_xor_sync(0xffu, a, 1);
        a += __shfl_xor_sync(0xffu, a, 2);
        a += __shfl_xor_sync(0xffu, a, 4);
        d += __shfl_xor_sync(0xffu, d, 1);
        d += __shfl_xor_sync(0xffu, d, 2);
        d += __shfl_xor_sync(0xffu, d, 4);
        if (lane == 0) { g_as2[n] = a; g_ad2[n] = d; }
    }
}

// ========== l2: single-pass softmax+aggregate ==============================
__global__ __launch_bounds__(256) void l2_kernel(float* __restrict__ out,
                                                 const float* __restrict__ b2)
{
    int t = threadIdx.x, wid = t >> 5, lane = t & 31;
    int n = blockIdx.x * 8 + wid;
    int off = g_off[n], deg = g_degN[n];
    int c8 = lane & 7, g4 = lane >> 3;
    float adn = g_ad2[n];

    float acc = 0.f, sum = 0.f;
    for (int base = 0; base < deg; base += 32) {
        int sjv = 0;
        bool inr = (base + lane < deg);
        if (inr) sjv = g_csr[off + base + lane];
        float v = g_as2[sjv] + adn;
        v = fmaxf(v, 0.2f * v);
        float p = inr ? __expf(v) : 0.f;       // 32 edges per MUFU
        sum += p;
#pragma unroll
        for (int j = 0; j < 8; j++) {
            if (base + (j << 2) >= deg) break;
            int sl = (j << 2) + g4;
            int s = __shfl_sync(0xffffffffu, sjv, sl);
            float pb = __shfl_sync(0xffffffffu, p, sl);
            acc = fmaf(pb, g_xp2[(size_t)s * 8 + c8], acc);
        }
    }
    sum += __shfl_xor_sync(0xffffffffu, sum, 1);
    sum += __shfl_xor_sync(0xffffffffu, sum, 2);
    sum += __shfl_xor_sync(0xffffffffu, sum, 4);
    sum += __shfl_xor_sync(0xffffffffu, sum, 8);
    sum += __shfl_xor_sync(0xffffffffu, sum, 16);
    float invd = 1.f / sum;
    acc += __shfl_xor_sync(0xffffffffu, acc, 8);
    acc += __shfl_xor_sync(0xffffffffu, acc, 16);
    if (lane < 8) out[(size_t)n * 8 + lane] = fmaf(acc, invd, b2[lane]);
}

// ---------------------------------------------------------------------------
extern "C" void kernel_launch(void* const* d_in, const int* in_sizes, int n_in,
                              void* d_out, int out_size) {
    const float* x        = (const float*)d_in[0];
    const int*   eidx     = (const int*)d_in[1];
    const float* W1       = (const float*)d_in[2];
    const float* att_src1 = (const float*)d_in[3];
    const float* att_dst1 = (const float*)d_in[4];
    const float* b1       = (const float*)d_in[5];
    const float* W2       = (const float*)d_in[6];
    const float* att_src2 = (const float*)d_in[7];
    const float* att_dst2 = (const float*)d_in[8];
    const float* b2       = (const float*)d_in[9];
    float* out = (float*)d_out;

    int E = in_sizes[1] / 2;
    const int* src = eidx;
    const int* dst = eidx + E;

    k1_gemm_count<<<GEMMB + CNTB, 256>>>(x, W1, att_src1, att_dst1, dst, E);
    alloc_kernel<<<(NN + 255) / 256, 256>>>();
    scatter_kernel<<<(E + 255) / 256, 256>>>(src, dst, E);
    l1_kernel<<<NN / 8, 256>>>(b1, W2, att_src2, att_dst2);
    l2_kernel<<<NN / 8, 256>>>(out, b2);
}

// round 4
// speedup vs baseline: 1.2168x; 1.0404x over previous
#include <cuda_runtime.h>
#include <cuda_bf16.h>
#include <math.h>

#define NN 100000
#define EE 3200000
#define NEMAX (EE + NN + 8 * NN)   // padded CSR (segments rounded up to 8)
#define GEMMB 391          // ceil(NN/256) gemm blocks (256 rows each)
#define CNTB 256           // count blocks fused into k1
#define PADT 260           // padded row length of transposed x tile (even!)

typedef unsigned long long ull;

// ---------------- scratch (device globals; no allocation allowed) ----------
__device__ float g_xp1[NN * 32];   // x @ W1
__device__ float g_as1[NN * 4];
__device__ float g_ad1[NN * 4];
__device__ float g_xp2[NN * 8];    // h @ W2
__device__ float g_as2[NN];
__device__ float g_ad2[NN];
__device__ int   g_deg[NN];        // zero-init; reset to 0 by alloc each run
__device__ int   g_degN[NN];       // real degree incl self-loop
__device__ int   g_off[NN];
__device__ int   g_pos[NN];
__device__ int   g_csr[NEMAX];
__device__ int   g_total;          // zero-init; reset to 0 by scatter each run

// ---------------- packed f32x2 helpers ------------------------------------
__device__ __forceinline__ ull dup2(float v) {
    ull r; unsigned u = __float_as_uint(v);
    asm("mov.b64 %0, {%1, %1};" : "=l"(r) : "r"(u));
    return r;
}
__device__ __forceinline__ ull fma2(ull a, ull b, ull c) {
    ull d;
    asm("fma.rn.f32x2 %0, %1, %2, %3;" : "=l"(d) : "l"(a), "l"(b), "l"(c));
    return d;
}
__device__ __forceinline__ void unpack2(ull v, float& lo, float& hi) {
    unsigned a, b;
    asm("mov.b64 {%0, %1}, %2;" : "=r"(a), "=r"(b) : "l"(v));
    lo = __uint_as_float(a); hi = __uint_as_float(b);
}

// ============ K1: fused [GEMM1 + attn1 epilogue] & [degree count] ==========
__global__ __launch_bounds__(256) void k1_gemm_count(
    const float* __restrict__ x, const float* __restrict__ W,
    const float* __restrict__ as1, const float* __restrict__ ad1,
    const int* __restrict__ dst, int E)
{
    if (blockIdx.x >= GEMMB) {                 // ---- count blocks ----
        int i = (blockIdx.x - GEMMB) * 256 + threadIdx.x;
        for (; i < E; i += CNTB * 256) atomicAdd(&g_deg[dst[i]], 1);
        return;
    }
    __shared__ float xs[32 * PADT];            // [k][row] transposed
    __shared__ float ws[32 * 32];              // [k][col]
    int t = threadIdx.x;
    int row0 = blockIdx.x * 256;
    int rg  = t >> 3;                          // 0..31 -> rows rg*8..rg*8+7
    int cg4 = (t & 7) << 2;                    // 0,4,...,28 col base

    ull acc[4][4];
#pragma unroll
    for (int p = 0; p < 4; p++)
#pragma unroll
        for (int c = 0; c < 4; c++) acc[p][c] = 0ull;

    for (int kk = 0; kk < 512; kk += 32) {
#pragma unroll
        for (int i = 0; i < 8; i++) {
            int lf  = i * 256 + t;
            int row = lf >> 3;
            int k4  = (lf & 7) << 2;
            float4 v = make_float4(0.f, 0.f, 0.f, 0.f);
            int grow = row0 + row;
            if (grow < NN)
                v = *(const float4*)(x + (size_t)grow * 512 + kk + k4);
            xs[(k4 + 0) * PADT + row] = v.x;
            xs[(k4 + 1) * PADT + row] = v.y;
            xs[(k4 + 2) * PADT + row] = v.z;
            xs[(k4 + 3) * PADT + row] = v.w;
        }
        {
            int r = t >> 3, k4 = (t & 7) << 2;
            *(float4*)&ws[r * 32 + k4] = *(const float4*)(W + (size_t)(kk + r) * 32 + k4);
        }
        __syncthreads();
#pragma unroll
        for (int k = 0; k < 32; k++) {
            float4 wv = *(float4*)&ws[k * 32 + cg4];
            ull w0 = dup2(wv.x), w1 = dup2(wv.y), w2 = dup2(wv.z), w3 = dup2(wv.w);
            const ull* xr = (const ull*)&xs[k * PADT + (rg << 3)];
            ull x0 = xr[0], x1 = xr[1], x2 = xr[2], x3 = xr[3];
            acc[0][0] = fma2(x0, w0, acc[0][0]); acc[0][1] = fma2(x0, w1, acc[0][1]);
            acc[0][2] = fma2(x0, w2, acc[0][2]); acc[0][3] = fma2(x0, w3, acc[0][3]);
            acc[1][0] = fma2(x1, w0, acc[1][0]); acc[1][1] = fma2(x1, w1, acc[1][1]);
            acc[1][2] = fma2(x1, w2, acc[1][2]); acc[1][3] = fma2(x1, w3, acc[1][3]);
            acc[2][0] = fma2(x2, w0, acc[2][0]); acc[2][1] = fma2(x2, w1, acc[2][1]);
            acc[2][2] = fma2(x2, w2, acc[2][2]); acc[2][3] = fma2(x2, w3, acc[2][3]);
            acc[3][0] = fma2(x3, w0, acc[3][0]); acc[3][1] = fma2(x3, w1, acc[3][1]);
            acc[3][2] = fma2(x3, w2, acc[3][2]); acc[3][3] = fma2(x3, w3, acc[3][3]);
        }
        __syncthreads();
    }

    int head = cg4 >> 3;
    int half = (cg4 >> 2) & 1;
    float a_s[4], a_d[4];
#pragma unroll
    for (int c = 0; c < 4; c++) {
        a_s[c] = as1[head * 8 + half * 4 + c];
        a_d[c] = ad1[head * 8 + half * 4 + c];
    }
#pragma unroll
    for (int p = 0; p < 4; p++) {
        float o0[4], o1[4];
#pragma unroll
        for (int c = 0; c < 4; c++) unpack2(acc[p][c], o0[c], o1[c]);
#pragma unroll
        for (int rr = 0; rr < 2; rr++) {
            float* o = rr ? o1 : o0;
            int row = row0 + (rg << 3) + (p << 1) + rr;
            float sv = o[0]*a_s[0] + o[1]*a_s[1] + o[2]*a_s[2] + o[3]*a_s[3];
            float dv = o[0]*a_d[0] + o[1]*a_d[1] + o[2]*a_d[2] + o[3]*a_d[3];
            sv += __shfl_xor_sync(0xffffffffu, sv, 1);
            dv += __shfl_xor_sync(0xffffffffu, dv, 1);
            if (row < NN) {
                *(float4*)(g_xp1 + (size_t)row * 32 + cg4) =
                    make_float4(o[0], o[1], o[2], o[3]);
                if (half == 0) g_as1[row * 4 + head] = sv;
                else           g_ad1[row * 4 + head] = dv;
            }
        }
    }
}

// ------ CSR alloc: pad each segment to multiple of 8, reset g_deg ----------
__global__ void alloc_kernel() {
    int n = blockIdx.x * blockDim.x + threadIdx.x;
    int lane = threadIdx.x & 31;
    int deg = (n < NN) ? g_deg[n] + 1 : 0;     // +1 self-loop
    int degP = (deg + 7) & ~7;                 // padded
    int scan = degP;
#pragma unroll
    for (int d = 1; d < 32; d <<= 1) {
        int tv = __shfl_up_sync(0xffffffffu, scan, d);
        if (lane >= d) scan += tv;
    }
    int total = __shfl_sync(0xffffffffu, scan, 31);
    int base = 0;
    if (lane == 31) base = atomicAdd(&g_total, total);
    base = __shfl_sync(0xffffffffu, base, 31);
    int off = base + scan - degP;
    if (n < NN) {
        g_off[n]  = off;
        g_csr[off] = n;                        // self-loop in slot 0
        g_pos[n]  = off + 1;
        g_degN[n] = deg;
        for (int i = deg; i < degP; i++) g_csr[off + i] = n;  // pads (p will be 0)
        g_deg[n]  = 0;                          // ready for next replay
    }
}

__global__ void scatter_kernel(const int* __restrict__ src,
                               const int* __restrict__ dst, int E) {
    if (blockIdx.x == 0 && threadIdx.x == 0) g_total = 0;
    int i = blockIdx.x * blockDim.x + threadIdx.x;
    if (i >= E) return;
    int d = dst[i];
    int slot = atomicAdd(&g_pos[d], 1);
    g_csr[slot] = src[i];
}

// ========== l1: branch-free 8-edge chunks, fused ELU + xp2/as2/ad2 =========
__global__ __launch_bounds__(256) void l1_kernel(
    const float* __restrict__ b1, const float* __restrict__ W2,
    const float* __restrict__ as2v, const float* __restrict__ ad2v)
{
    __shared__ float W2s[256];
    __shared__ float hs[8][33];
    int t = threadIdx.x;
    W2s[t] = W2[t];
    __syncthreads();

    int wid = t >> 5, lane = t & 31;
    int n = blockIdx.x * 8 + wid;              // grid 12500*8 == NN exactly
    int off = g_off[n], deg = g_degN[n];
    int degP = (deg + 7) & ~7;
    int hh = lane & 3, j4 = lane >> 2, hsel = lane >> 3;
    float adh = g_ad1[n * 4 + hh];
    const float* xp1l = g_xp1 + lane;

    float acc = 0.f, sum = 0.f;
    for (int base = 0; base < degP; base += 8) {
        int s8 = g_csr[off + base + j4];        // 8 srcs, 4-way dup
        float v = g_as1[s8 * 4 + hh] + adh;
        v = fmaxf(v, 0.2f * v);                 // leaky relu
        float p = (base + j4 < deg) ? __expf(v) : 0.f;
        sum += p;
#pragma unroll
        for (int j = 0; j < 8; j++) {
            int s = __shfl_sync(0xffffffffu, s8, j << 2);
            float pb = __shfl_sync(0xffffffffu, p, (j << 2) | hsel);
            acc = fmaf(pb, xp1l[(size_t)s * 32], acc);
        }
    }
    // per-head denominators (reduce over j4 lanes)
    sum += __shfl_xor_sync(0xffffffffu, sum, 4);
    sum += __shfl_xor_sync(0xffffffffu, sum, 8);
    sum += __shfl_xor_sync(0xffffffffu, sum, 16);
    float invd = 1.f / sum;                     // lane's value = head (lane&3)
    float invs = __shfl_sync(0xffffffffu, invd, hsel);
    float o = fmaf(acc, invs, b1[lane]);
    float hval = o > 0.f ? o : expm1f(o);       // ELU

    // fused xp2 = h @ W2, plus as2/ad2
    hs[wid][lane] = hval;
    __syncwarp();
    if (lane < 8) {
        float s2 = 0.f;
#pragma unroll
        for (int k2 = 0; k2 < 32; k2++)
            s2 = fmaf(hs[wid][k2], W2s[k2 * 8 + lane], s2);
        g_xp2[(size_t)n * 8 + lane] = s2;
        float a = s2 * as2v[lane], d = s2 * ad2v[lane];
        a += __shfl_xor_sync(0xffu, a, 1);
        a += __shfl_xor_sync(0xffu, a, 2);
        a += __shfl_xor_sync(0xffu, a, 4);
        d += __shfl_xor_sync(0xffu, d, 1);
        d += __shfl_xor_sync(0xffu, d, 2);
        d += __shfl_xor_sync(0xffu, d, 4);
        if (lane == 0) { g_as2[n] = a; g_ad2[n] = d; }
    }
}

// ========== l2: branch-free 8-edge chunks ==================================
__global__ __launch_bounds__(256) void l2_kernel(float* __restrict__ out,
                                                 const float* __restrict__ b2)
{
    int t = threadIdx.x, wid = t >> 5, lane = t & 31;
    int n = blockIdx.x * 8 + wid;
    int off = g_off[n], deg = g_degN[n];
    int degP = (deg + 7) & ~7;
    int c8 = lane & 7, g4 = lane >> 3;
    float adn = g_ad2[n];

    float acc = 0.f, sum = 0.f;
    for (int base = 0; base < degP; base += 8) {
        int sv = g_csr[off + base + c8];        // edge j = lane&7 (4-way dup)
        float v = g_as2[sv] + adn;
        v = fmaxf(v, 0.2f * v);
        float p = (base + c8 < deg) ? __expf(v) : 0.f;
        sum += p;                                // 4x-duplicated sum
#pragma unroll
        for (int i = 0; i < 2; i++) {
            int j = (i << 2) + g4;
            int s = __shfl_sync(0xffffffffu, sv, j);
            float pb = __shfl_sync(0xffffffffu, p, j);
            acc = fmaf(pb, g_xp2[(size_t)s * 8 + c8], acc);
        }
    }
    sum += __shfl_xor_sync(0xffffffffu, sum, 1);
    sum += __shfl_xor_sync(0xffffffffu, sum, 2);
    sum += __shfl_xor_sync(0xffffffffu, sum, 4);
    sum += __shfl_xor_sync(0xffffffffu, sum, 8);
    sum += __shfl_xor_sync(0xffffffffu, sum, 16);
    float invd = 4.f / sum;                      // sum is 4x the true total
    acc += __shfl_xor_sync(0xffffffffu, acc, 8);
    acc += __shfl_xor_sync(0xffffffffu, acc, 16);
    if (lane < 8) out[(size_t)n * 8 + lane] = fmaf(acc, invd, b2[lane]);
}

// ---------------------------------------------------------------------------
extern "C" void kernel_launch(void* const* d_in, const int* in_sizes, int n_in,
                              void* d_out, int out_size) {
    const float* x        = (const float*)d_in[0];
    const int*   eidx     = (const int*)d_in[1];
    const float* W1       = (const float*)d_in[2];
    const float* att_src1 = (const float*)d_in[3];
    const float* att_dst1 = (const float*)d_in[4];
    const float* b1       = (const float*)d_in[5];
    const float* W2       = (const float*)d_in[6];
    const float* att_src2 = (const float*)d_in[7];
    const float* att_dst2 = (const float*)d_in[8];
    const float* b2       = (const float*)d_in[9];
    float* out = (float*)d_out;

    int E = in_sizes[1] / 2;
    const int* src = eidx;
    const int* dst = eidx + E;

    k1_gemm_count<<<GEMMB + CNTB, 256>>>(x, W1, att_src1, att_dst1, dst, E);
    alloc_kernel<<<(NN + 255) / 256, 256>>>();
    scatter_kernel<<<(E + 255) / 256, 256>>>(src, dst, E);
    l1_kernel<<<NN / 8, 256>>>(b1, W2, att_src2, att_dst2);
    l2_kernel<<<NN / 8, 256>>>(out, b2);
}

// round 6
// speedup vs baseline: 1.3517x; 1.1109x over previous
#include <cuda_runtime.h>
#include <cuda_bf16.h>
#include <math.h>

#define NN 100000
#define EE 3200000
#define NEMAX (EE + NN + 8 * NN)   // padded CSR (segments rounded up to 8)
#define GEMMB 391          // ceil(NN/256) gemm blocks (256 rows each)
#define CNTB 256           // count blocks fused into k1
#define PADT 260           // padded row length of transposed x tile (even!)

typedef unsigned long long ull;

// ---------------- scratch (device globals; no allocation allowed) ----------
__device__ __align__(16) float g_xp1[NN * 32];   // x @ W1
__device__ float g_as1[NN * 4];
__device__ float g_ad1[NN * 4];
__device__ __align__(16) float g_xp2[NN * 8];    // h @ W2
__device__ float g_as2[NN];
__device__ float g_ad2[NN];
__device__ int   g_deg[NN];        // zero-init; reset to 0 by alloc each run
__device__ int   g_degN[NN];       // real degree incl self-loop
__device__ int   g_off[NN];
__device__ int   g_pos[NN];
__device__ int   g_csr[NEMAX];
__device__ int   g_total;          // zero-init; reset to 0 by scatter each run

// ---------------- packed f32x2 helpers ------------------------------------
__device__ __forceinline__ ull dup2(float v) {
    ull r; unsigned u = __float_as_uint(v);
    asm("mov.b64 %0, {%1, %1};" : "=l"(r) : "r"(u));
    return r;
}
__device__ __forceinline__ ull fma2(ull a, ull b, ull c) {
    ull d;
    asm("fma.rn.f32x2 %0, %1, %2, %3;" : "=l"(d) : "l"(a), "l"(b), "l"(c));
    return d;
}
__device__ __forceinline__ void unpack2(ull v, float& lo, float& hi) {
    unsigned a, b;
    asm("mov.b64 {%0, %1}, %2;" : "=r"(a), "=r"(b) : "l"(v));
    lo = __uint_as_float(a); hi = __uint_as_float(b);
}

// ============ K1: fused [GEMM1 + attn1 epilogue] & [degree count] ==========
__global__ __launch_bounds__(256) void k1_gemm_count(
    const float* __restrict__ x, const float* __restrict__ W,
    const float* __restrict__ as1, const float* __restrict__ ad1,
    const int* __restrict__ dst, int E)
{
    if (blockIdx.x >= GEMMB) {                 // ---- count blocks ----
        int i = (blockIdx.x - GEMMB) * 256 + threadIdx.x;
        for (; i < E; i += CNTB * 256) atomicAdd(&g_deg[dst[i]], 1);
        return;
    }
    __shared__ float xs[32 * PADT];            // [k][row] transposed
    __shared__ float ws[32 * 32];              // [k][col]
    int t = threadIdx.x;
    int row0 = blockIdx.x * 256;
    int rg  = t >> 3;                          // 0..31 -> rows rg*8..rg*8+7
    int cg4 = (t & 7) << 2;                    // 0,4,...,28 col base

    ull acc[4][4];
#pragma unroll
    for (int p = 0; p < 4; p++)
#pragma unroll
        for (int c = 0; c < 4; c++) acc[p][c] = 0ull;

    for (int kk = 0; kk < 512; kk += 32) {
#pragma unroll
        for (int i = 0; i < 8; i++) {
            int lf  = i * 256 + t;
            int row = lf >> 3;
            int k4  = (lf & 7) << 2;
            float4 v = make_float4(0.f, 0.f, 0.f, 0.f);
            int grow = row0 + row;
            if (grow < NN)
                v = *(const float4*)(x + (size_t)grow * 512 + kk + k4);
            xs[(k4 + 0) * PADT + row] = v.x;
            xs[(k4 + 1) * PADT + row] = v.y;
            xs[(k4 + 2) * PADT + row] = v.z;
            xs[(k4 + 3) * PADT + row] = v.w;
        }
        {
            int r = t >> 3, k4 = (t & 7) << 2;
            *(float4*)&ws[r * 32 + k4] = *(const float4*)(W + (size_t)(kk + r) * 32 + k4);
        }
        __syncthreads();
#pragma unroll
        for (int k = 0; k < 32; k++) {
            float4 wv = *(float4*)&ws[k * 32 + cg4];
            ull w0 = dup2(wv.x), w1 = dup2(wv.y), w2 = dup2(wv.z), w3 = dup2(wv.w);
            const ull* xr = (const ull*)&xs[k * PADT + (rg << 3)];
            ull x0 = xr[0], x1 = xr[1], x2 = xr[2], x3 = xr[3];
            acc[0][0] = fma2(x0, w0, acc[0][0]); acc[0][1] = fma2(x0, w1, acc[0][1]);
            acc[0][2] = fma2(x0, w2, acc[0][2]); acc[0][3] = fma2(x0, w3, acc[0][3]);
            acc[1][0] = fma2(x1, w0, acc[1][0]); acc[1][1] = fma2(x1, w1, acc[1][1]);
            acc[1][2] = fma2(x1, w2, acc[1][2]); acc[1][3] = fma2(x1, w3, acc[1][3]);
            acc[2][0] = fma2(x2, w0, acc[2][0]); acc[2][1] = fma2(x2, w1, acc[2][1]);
            acc[2][2] = fma2(x2, w2, acc[2][2]); acc[2][3] = fma2(x2, w3, acc[2][3]);
            acc[3][0] = fma2(x3, w0, acc[3][0]); acc[3][1] = fma2(x3, w1, acc[3][1]);
            acc[3][2] = fma2(x3, w2, acc[3][2]); acc[3][3] = fma2(x3, w3, acc[3][3]);
        }
        __syncthreads();
    }

    int head = cg4 >> 3;
    int half = (cg4 >> 2) & 1;
    float a_s[4], a_d[4];
#pragma unroll
    for (int c = 0; c < 4; c++) {
        a_s[c] = as1[head * 8 + half * 4 + c];
        a_d[c] = ad1[head * 8 + half * 4 + c];
    }
#pragma unroll
    for (int p = 0; p < 4; p++) {
        float o0[4], o1[4];
#pragma unroll
        for (int c = 0; c < 4; c++) unpack2(acc[p][c], o0[c], o1[c]);
#pragma unroll
        for (int rr = 0; rr < 2; rr++) {
            float* o = rr ? o1 : o0;
            int row = row0 + (rg << 3) + (p << 1) + rr;
            float sv = o[0]*a_s[0] + o[1]*a_s[1] + o[2]*a_s[2] + o[3]*a_s[3];
            float dv = o[0]*a_d[0] + o[1]*a_d[1] + o[2]*a_d[2] + o[3]*a_d[3];
            sv += __shfl_xor_sync(0xffffffffu, sv, 1);
            dv += __shfl_xor_sync(0xffffffffu, dv, 1);
            if (row < NN) {
                *(float4*)(g_xp1 + (size_t)row * 32 + cg4) =
                    make_float4(o[0], o[1], o[2], o[3]);
                if (half == 0) g_as1[row * 4 + head] = sv;
                else           g_ad1[row * 4 + head] = dv;
            }
        }
    }
}

// ------ CSR alloc: pad each segment to multiple of 8, reset g_deg ----------
__global__ void alloc_kernel() {
    int n = blockIdx.x * blockDim.x + threadIdx.x;
    int lane = threadIdx.x & 31;
    int deg = (n < NN) ? g_deg[n] + 1 : 0;     // +1 self-loop
    int degP = (deg + 7) & ~7;                 // padded
    int scan = degP;
#pragma unroll
    for (int d = 1; d < 32; d <<= 1) {
        int tv = __shfl_up_sync(0xffffffffu, scan, d);
        if (lane >= d) scan += tv;
    }
    int total = __shfl_sync(0xffffffffu, scan, 31);
    int base = 0;
    if (lane == 31) base = atomicAdd(&g_total, total);
    base = __shfl_sync(0xffffffffu, base, 31);
    int off = base + scan - degP;
    if (n < NN) {
        g_off[n]  = off;
        g_csr[off] = n;                        // self-loop in slot 0
        g_pos[n]  = off + 1;
        g_degN[n] = deg;
        for (int i = deg; i < degP; i++) g_csr[off + i] = n;  // pads (p = 0)
        g_deg[n]  = 0;                          // ready for next replay
    }
}

__global__ void scatter_kernel(const int* __restrict__ src,
                               const int* __restrict__ dst, int E) {
    if (blockIdx.x == 0 && threadIdx.x == 0) g_total = 0;
    int i = blockIdx.x * blockDim.x + threadIdx.x;
    if (i >= E) return;
    int d = dst[i];
    int slot = atomicAdd(&g_pos[d], 1);
    g_csr[slot] = src[i];
}

// == l1: float4 gathers, 4 L1-slots/8-edges, fused ELU + xp2/as2/ad2 ========
__global__ __launch_bounds__(256) void l1_kernel(
    const float* __restrict__ b1, const float* __restrict__ W2,
    const float* __restrict__ as2v, const float* __restrict__ ad2v)
{
    __shared__ float W2s[256];
    __shared__ float hs[8][36];
    int t = threadIdx.x;
    W2s[t] = W2[t];
    __syncthreads();

    int wid = t >> 5, lane = t & 31;
    int n = blockIdx.x * 8 + wid;              // grid 12500*8 == NN exactly
    int off = g_off[n], deg = g_degN[n];
    int degP = (deg + 7) & ~7;
    int hh = lane & 3, j4 = lane >> 2;         // exp layout: edge j4, head hh
    int q  = lane >> 3, c4 = lane & 7;         // acc layout: subgroup q, quad c4
    float adh = g_ad1[n * 4 + hh];
    int ssrc = q << 2;                         // shfl src for s (round 0)
    int psrc = (q << 2) + (c4 >> 1);           // shfl src for p (round 0)
    const float* xp1q = g_xp1 + (c4 << 2);

    float4 acc = make_float4(0.f, 0.f, 0.f, 0.f);
    float sum = 0.f;
    for (int base = 0; base < degP; base += 8) {
        int s8 = g_csr[off + base + j4];        // 8 srcs, 4-way dup
        float v = g_as1[s8 * 4 + hh] + adh;
        v = fmaxf(v, 0.2f * v);                 // leaky relu
        float p = (base + j4 < deg) ? __expf(v) : 0.f;
        sum += p;
#pragma unroll
        for (int r = 0; r < 2; r++) {
            int   s  = __shfl_sync(0xffffffffu, s8, ssrc + (r << 4));
            float pb = __shfl_sync(0xffffffffu, p,  psrc + (r << 4));
            float4 xv = *(const float4*)(xp1q + (size_t)s * 32);
            acc.x = fmaf(pb, xv.x, acc.x);
            acc.y = fmaf(pb, xv.y, acc.y);
            acc.z = fmaf(pb, xv.z, acc.z);
            acc.w = fmaf(pb, xv.w, acc.w);
        }
    }
    // per-head denominators (reduce over edge lanes j4)
    sum += __shfl_xor_sync(0xffffffffu, sum, 4);
    sum += __shfl_xor_sync(0xffffffffu, sum, 8);
    sum += __shfl_xor_sync(0xffffffffu, sum, 16);
    float invd = 1.f / sum;                     // lane holds head (lane&3)
    float invs = __shfl_sync(0xffffffffu, invd, c4 >> 1);
    // reduce acc over subgroups q
    acc.x += __shfl_xor_sync(0xffffffffu, acc.x, 8);
    acc.y += __shfl_xor_sync(0xffffffffu, acc.y, 8);
    acc.z += __shfl_xor_sync(0xffffffffu, acc.z, 8);
    acc.w += __shfl_xor_sync(0xffffffffu, acc.w, 8);
    acc.x += __shfl_xor_sync(0xffffffffu, acc.x, 16);
    acc.y += __shfl_xor_sync(0xffffffffu, acc.y, 16);
    acc.z += __shfl_xor_sync(0xffffffffu, acc.z, 16);
    acc.w += __shfl_xor_sync(0xffffffffu, acc.w, 16);

    if (q == 0) {                               // lanes 0..7 hold all quads
        float4 bv = *(const float4*)(b1 + (c4 << 2));
        float o0 = fmaf(acc.x, invs, bv.x);
        float o1 = fmaf(acc.y, invs, bv.y);
        float o2 = fmaf(acc.z, invs, bv.z);
        float o3 = fmaf(acc.w, invs, bv.w);
        o0 = o0 > 0.f ? o0 : expm1f(o0);
        o1 = o1 > 0.f ? o1 : expm1f(o1);
        o2 = o2 > 0.f ? o2 : expm1f(o2);
        o3 = o3 > 0.f ? o3 : expm1f(o3);
        *(float4*)&hs[wid][c4 << 2] = make_float4(o0, o1, o2, o3);
    }
    __syncwarp();

    // fused xp2 = h @ W2, plus as2/ad2
    if (lane < 8) {
        float s2 = 0.f;
#pragma unroll
        for (int k2 = 0; k2 < 32; k2++)
            s2 = fmaf(hs[wid][k2], W2s[k2 * 8 + lane], s2);
        g_xp2[(size_t)n * 8 + lane] = s2;
        float a = s2 * as2v[lane], d = s2 * ad2v[lane];
        a += __shfl_xor_sync(0xffu, a, 1);
        a += __shfl_xor_sync(0xffu, a, 2);
        a += __shfl_xor_sync(0xffu, a, 4);
        d += __shfl_xor_sync(0xffu, d, 1);
        d += __shfl_xor_sync(0xffu, d, 2);
        d += __shfl_xor_sync(0xffu, d, 4);
        if (lane == 0) { g_as2[n] = a; g_ad2[n] = d; }
    }
}

// ========== l2: zero-shuffle hot loop, float2 gathers ======================
__global__ __launch_bounds__(256) void l2_kernel(float* __restrict__ out,
                                                 const float* __restrict__ b2)
{
    int t = threadIdx.x, wid = t >> 5, lane = t & 31;
    int n = blockIdx.x * 8 + wid;
    int off = g_off[n], deg = g_degN[n];
    int degP = (deg + 7) & ~7;
    int j8 = lane >> 2, c2 = lane & 3;          // edge j8, channel-pair c2
    float adn = g_ad2[n];
    const float* xp2p = g_xp2 + (c2 << 1);

    float2 acc = make_float2(0.f, 0.f);
    float sum = 0.f;
    for (int base = 0; base < degP; base += 8) {
        int sv = g_csr[off + base + j8];         // 8 distinct, 4-way dup
        float v = g_as2[sv] + adn;
        v = fmaxf(v, 0.2f * v);
        float p = (base + j8 < deg) ? __expf(v) : 0.f;
        sum += p;                                 // each edge once per lane-row
        float2 xv = *(const float2*)(xp2p + (size_t)sv * 8);
        acc.x = fmaf(p, xv.x, acc.x);
        acc.y = fmaf(p, xv.y, acc.y);
    }
    // reduce over edge lanes j8 (bits 2,3,4)
    sum   += __shfl_xor_sync(0xffffffffu, sum, 4);
    acc.x += __shfl_xor_sync(0xffffffffu, acc.x, 4);
    acc.y += __shfl_xor_sync(0xffffffffu, acc.y, 4);
    sum   += __shfl_xor_sync(0xffffffffu, sum, 8);
    acc.x += __shfl_xor_sync(0xffffffffu, acc.x, 8);
    acc.y += __shfl_xor_sync(0xffffffffu, acc.y, 8);
    sum   += __shfl_xor_sync(0xffffffffu, sum, 16);
    acc.x += __shfl_xor_sync(0xffffffffu, acc.x, 16);
    acc.y += __shfl_xor_sync(0xffffffffu, acc.y, 16);
    float invd = 1.f / sum;
    if (lane < 4) {
        float2 bv = *(const float2*)(b2 + (c2 << 1));
        float2 ov;
        ov.x = fmaf(acc.x, invd, bv.x);
        ov.y = fmaf(acc.y, invd, bv.y);
        *(float2*)(out + (size_t)n * 8 + (c2 << 1)) = ov;
    }
}

// ---------------------------------------------------------------------------
extern "C" void kernel_launch(void* const* d_in, const int* in_sizes, int n_in,
                              void* d_out, int out_size) {
    const float* x        = (const float*)d_in[0];
    const int*   eidx     = (const int*)d_in[1];
    const float* W1       = (const float*)d_in[2];
    const float* att_src1 = (const float*)d_in[3];
    const float* att_dst1 = (const float*)d_in[4];
    const float* b1       = (const float*)d_in[5];
    const float* W2       = (const float*)d_in[6];
    const float* att_src2 = (const float*)d_in[7];
    const float* att_dst2 = (const float*)d_in[8];
    const float* b2       = (const float*)d_in[9];
    float* out = (float*)d_out;

    int E = in_sizes[1] / 2;
    const int* src = eidx;
    const int* dst = eidx + E;

    k1_gemm_count<<<GEMMB + CNTB, 256>>>(x, W1, att_src1, att_dst1, dst, E);
    alloc_kernel<<<(NN + 255) / 256, 256>>>();
    scatter_kernel<<<(E + 255) / 256, 256>>>(src, dst, E);
    l1_kernel<<<NN / 8, 256>>>(b1, W2, att_src2, att_dst2);
    l2_kernel<<<NN / 8, 256>>>(out, b2);
}